// round 1
// baseline (speedup 1.0000x reference)
#include <cuda_runtime.h>

#define N0 100000
#define WBAG 16
#define N1V 25000
#define N2V 5000
#define E1V 500000
#define E2V 100000
#define C 128

// ---------------- scratch (alloc-free rule: __device__ globals) ----------------
__device__ float g_h0[N0 * C];
__device__ float g_h1[N1V * C];
__device__ float g_agg1[N1V * C];
__device__ float g_cnt1[N1V];
__device__ float g_agg2[N2V * C];
__device__ float g_cnt2[N2V];

// ---------------- zero the aggregation buffers ----------------
__global__ void zero_kernel() {
    const int stride = gridDim.x * blockDim.x;
    int i = blockIdx.x * blockDim.x + threadIdx.x;
    const int tot4 = (N1V * C + N2V * C) / 4;   // 960000 float4s
    const int a1_4 = (N1V * C) / 4;             // 800000
    float4 z = make_float4(0.f, 0.f, 0.f, 0.f);
    for (int t = i; t < tot4; t += stride) {
        if (t < a1_4) ((float4*)g_agg1)[t] = z;
        else          ((float4*)g_agg2)[t - a1_4] = z;
    }
    if (i < N1V) g_cnt1[i] = 0.f;
    if (i < N2V) g_cnt2[i] = 0.f;
}

// ---------------- embedding-bag sum + layernorm + relu ----------------
// one warp per output row; lane l owns channels [4l, 4l+4)
__global__ void embed_ln_relu(const int* __restrict__ x,
                              const float* __restrict__ emb,
                              const float* __restrict__ ln_g,
                              const float* __restrict__ ln_b) {
    int warp = (blockIdx.x * blockDim.x + threadIdx.x) >> 5;
    int lane = threadIdx.x & 31;
    if (warp >= N0) return;

    int idx_l = (lane < WBAG) ? x[warp * WBAG + lane] : 0;

    const float4* emb4 = (const float4*)emb;
    float4 acc = make_float4(0.f, 0.f, 0.f, 0.f);
#pragma unroll
    for (int w = 0; w < WBAG; w++) {
        int idx = __shfl_sync(0xffffffffu, idx_l, w);
        float4 v = emb4[idx * (C / 4) + lane];
        acc.x += v.x; acc.y += v.y; acc.z += v.z; acc.w += v.w;
    }

    // layernorm over 128 channels (E[x], E[x^2])
    float s  = acc.x + acc.y + acc.z + acc.w;
    float sq = acc.x * acc.x + acc.y * acc.y + acc.z * acc.z + acc.w * acc.w;
#pragma unroll
    for (int o = 16; o > 0; o >>= 1) {
        s  += __shfl_xor_sync(0xffffffffu, s,  o);
        sq += __shfl_xor_sync(0xffffffffu, sq, o);
    }
    float mu  = s * (1.0f / C);
    float var = sq * (1.0f / C) - mu * mu;
    float rs  = rsqrtf(var + 1e-5f);

    float4 gg = ((const float4*)ln_g)[lane];
    float4 bb = ((const float4*)ln_b)[lane];
    float4 o;
    o.x = fmaxf((acc.x - mu) * rs * gg.x + bb.x, 0.f);
    o.y = fmaxf((acc.y - mu) * rs * gg.y + bb.y, 0.f);
    o.z = fmaxf((acc.z - mu) * rs * gg.z + bb.z, 0.f);
    o.w = fmaxf((acc.w - mu) * rs * gg.w + bb.w, 0.f);
    ((float4*)g_h0)[warp * (C / 4) + lane] = o;
}

// ---------------- edge gather + atomic scatter-sum ----------------
// one warp per edge; lane l handles channels [4l, 4l+4)
__global__ void scatter_kernel(const int* __restrict__ src,
                               const int* __restrict__ dst, int E,
                               const float* __restrict__ h,
                               float* __restrict__ agg,
                               float* __restrict__ cnt) {
    int e = (blockIdx.x * blockDim.x + threadIdx.x) >> 5;
    int lane = threadIdx.x & 31;
    if (e >= E) return;
    int s = src[e];
    int d = dst[e];
    float4 v = ((const float4*)h)[s * (C / 4) + lane];
    float* a = agg + d * C + lane * 4;
    atomicAdd(a + 0, v.x);
    atomicAdd(a + 1, v.y);
    atomicAdd(a + 2, v.z);
    atomicAdd(a + 3, v.w);
    if (lane == 0) atomicAdd(&cnt[d], 1.0f);
}

// ---------------- fused SAGE linear: out = relu?( [mean||self] @ [Wl;Wr]^T + bl ) ----------------
// block: 256 threads, 32 rows x 128 cols per block; thread tile 4 rows x 4 cols.
// Wsh: [256][132] (transposed, padded stride kills bank conflicts on inner reads)
// Ish: [32][256]  (mean in k<128, self in k>=128)
#define WSTRIDE 132
__global__ void __launch_bounds__(256) finalize_kernel(
    const float* __restrict__ agg, const float* __restrict__ cnt,
    const float* __restrict__ hself,
    const float* __restrict__ Wl, const float* __restrict__ bl,
    const float* __restrict__ Wr,
    float* __restrict__ out, int n, int do_relu) {
    extern __shared__ float sm[];
    float* Wsh = sm;                       // 256*132 floats
    float* Ish = sm + 256 * WSTRIDE;       // 32*256 floats
    int tid = threadIdx.x;

    // stage weights transposed: Wsh[k][j] = W[j][k]
    for (int idx = tid; idx < C * C; idx += 256) {
        int j = idx >> 7;       // output col
        int k = idx & 127;      // input channel (coalesced in global)
        Wsh[k * WSTRIDE + j]         = Wl[idx];
        Wsh[(k + 128) * WSTRIDE + j] = Wr[idx];
    }

    int row0 = blockIdx.x * 32;
    // stage inputs: k<128 -> mean = agg/max(cnt,1); k>=128 -> self row
    for (int idx = tid; idx < 32 * 256; idx += 256) {
        int r = idx >> 8;
        int k = idx & 255;
        int row = row0 + r;
        float v = 0.f;
        if (row < n) {
            if (k < C) v = agg[row * C + k] / fmaxf(cnt[row], 1.0f);
            else       v = hself[row * C + (k - 128)];
        }
        Ish[r * 256 + k] = v;
    }
    __syncthreads();

    int tx = tid & 31;   // col group: cols [4tx, 4tx+4)
    int ty = tid >> 5;   // row group: rows [4ty, 4ty+4)
    float acc[4][4];
#pragma unroll
    for (int r = 0; r < 4; r++)
#pragma unroll
        for (int c = 0; c < 4; c++) acc[r][c] = 0.f;

    const float* Ib = Ish + (ty * 4) * 256;
    for (int k = 0; k < 256; k += 4) {
        float4 a4[4];
#pragma unroll
        for (int r = 0; r < 4; r++)
            a4[r] = *(const float4*)&Ib[r * 256 + k];   // broadcast across warp
#pragma unroll
        for (int kk = 0; kk < 4; kk++) {
            float4 w = *(const float4*)&Wsh[(k + kk) * WSTRIDE + tx * 4];
#pragma unroll
            for (int r = 0; r < 4; r++) {
                float a = (kk == 0) ? a4[r].x : (kk == 1) ? a4[r].y : (kk == 2) ? a4[r].z : a4[r].w;
                acc[r][0] += a * w.x;
                acc[r][1] += a * w.y;
                acc[r][2] += a * w.z;
                acc[r][3] += a * w.w;
            }
        }
    }

    float4 bb = *(const float4*)&bl[tx * 4];
#pragma unroll
    for (int r = 0; r < 4; r++) {
        int row = row0 + ty * 4 + r;
        if (row < n) {
            float4 o;
            o.x = acc[r][0] + bb.x;
            o.y = acc[r][1] + bb.y;
            o.z = acc[r][2] + bb.z;
            o.w = acc[r][3] + bb.w;
            if (do_relu) {
                o.x = fmaxf(o.x, 0.f); o.y = fmaxf(o.y, 0.f);
                o.z = fmaxf(o.z, 0.f); o.w = fmaxf(o.w, 0.f);
            }
            *(float4*)&out[row * C + tx * 4] = o;
        }
    }
}

// ---------------- launch ----------------
extern "C" void kernel_launch(void* const* d_in, const int* in_sizes, int n_in,
                              void* d_out, int out_size) {
    const int*   x    = (const int*)d_in[0];
    const int*   src1 = (const int*)d_in[1];
    const int*   dst1 = (const int*)d_in[2];
    const int*   src2 = (const int*)d_in[3];
    const int*   dst2 = (const int*)d_in[4];
    // d_in[5] = n1, d_in[6] = n2 (compile-time constants here)
    const float* emb  = (const float*)d_in[7];
    const float* ln_g = (const float*)d_in[8];
    const float* ln_b = (const float*)d_in[9];
    const float* Wl1  = (const float*)d_in[10];
    const float* bl1  = (const float*)d_in[11];
    const float* Wr1  = (const float*)d_in[12];
    const float* Wl2  = (const float*)d_in[13];
    const float* bl2  = (const float*)d_in[14];
    const float* Wr2  = (const float*)d_in[15];
    float* out = (float*)d_out;

    float *h0, *h1, *agg1, *cnt1, *agg2, *cnt2;
    cudaGetSymbolAddress((void**)&h0,   g_h0);
    cudaGetSymbolAddress((void**)&h1,   g_h1);
    cudaGetSymbolAddress((void**)&agg1, g_agg1);
    cudaGetSymbolAddress((void**)&cnt1, g_cnt1);
    cudaGetSymbolAddress((void**)&agg2, g_agg2);
    cudaGetSymbolAddress((void**)&cnt2, g_cnt2);

    size_t smem = (size_t)(256 * WSTRIDE + 32 * 256) * sizeof(float);
    cudaFuncSetAttribute(finalize_kernel,
                         cudaFuncAttributeMaxDynamicSharedMemorySize, (int)smem);

    // 1) zero aggregation buffers
    zero_kernel<<<512, 256>>>();
    // 2) embedding-bag + LN + relu -> g_h0
    embed_ln_relu<<<(N0 * 32 + 255) / 256, 256>>>(x, emb, ln_g, ln_b);
    // 3) conv1 scatter
    scatter_kernel<<<(E1V * 32 + 255) / 256, 256>>>(src1, dst1, E1V, h0, agg1, cnt1);
    // 4) conv1 linear + relu -> g_h1
    finalize_kernel<<<(N1V + 31) / 32, 256, smem>>>(agg1, cnt1, h0, Wl1, bl1, Wr1, h1, N1V, 1);
    // 5) conv2 scatter
    scatter_kernel<<<(E2V * 32 + 255) / 256, 256>>>(src2, dst2, E2V, h1, agg2, cnt2);
    // 6) conv2 linear -> d_out
    finalize_kernel<<<(N2V + 31) / 32, 256, smem>>>(agg2, cnt2, h1, Wl2, bl2, Wr2, out, N2V, 0);
}

// round 3
// speedup vs baseline: 1.8022x; 1.8022x over previous
#include <cuda_runtime.h>

#define N0 100000
#define WBAG 16
#define N1V 25000
#define N2V 5000
#define E1V 500000
#define E2V 100000
#define C 128

// ---------------- scratch (alloc-free rule: __device__ globals) ----------------
__device__ float g_h0[N0 * C];
__device__ float g_h1[N1V * C];
__device__ float g_agg1[N1V * C];
__device__ float g_cnt1[N1V];
__device__ float g_agg2[N2V * C];
__device__ float g_cnt2[N2V];

// ---------------- zero the aggregation buffers ----------------
__global__ void zero_kernel() {
    const int stride = gridDim.x * blockDim.x;
    int i = blockIdx.x * blockDim.x + threadIdx.x;
    const int tot4 = (N1V * C + N2V * C) / 4;
    const int a1_4 = (N1V * C) / 4;
    float4 z = make_float4(0.f, 0.f, 0.f, 0.f);
    for (int t = i; t < tot4; t += stride) {
        if (t < a1_4) ((float4*)g_agg1)[t] = z;
        else          ((float4*)g_agg2)[t - a1_4] = z;
    }
    if (i < N1V) g_cnt1[i] = 0.f;
    if (i < N2V) g_cnt2[i] = 0.f;
}

// ---------------- embedding-bag sum + layernorm + relu ----------------
__global__ void embed_ln_relu(const int* __restrict__ x,
                              const float* __restrict__ emb,
                              const float* __restrict__ ln_g,
                              const float* __restrict__ ln_b) {
    int warp = (blockIdx.x * blockDim.x + threadIdx.x) >> 5;
    int lane = threadIdx.x & 31;
    if (warp >= N0) return;

    int idx_l = (lane < WBAG) ? x[warp * WBAG + lane] : 0;

    const float4* emb4 = (const float4*)emb;
    float4 acc = make_float4(0.f, 0.f, 0.f, 0.f);
#pragma unroll
    for (int w = 0; w < WBAG; w++) {
        int idx = __shfl_sync(0xffffffffu, idx_l, w);
        float4 v = emb4[idx * (C / 4) + lane];
        acc.x += v.x; acc.y += v.y; acc.z += v.z; acc.w += v.w;
    }

    float s  = acc.x + acc.y + acc.z + acc.w;
    float sq = acc.x * acc.x + acc.y * acc.y + acc.z * acc.z + acc.w * acc.w;
#pragma unroll
    for (int o = 16; o > 0; o >>= 1) {
        s  += __shfl_xor_sync(0xffffffffu, s,  o);
        sq += __shfl_xor_sync(0xffffffffu, sq, o);
    }
    float mu  = s * (1.0f / C);
    float var = sq * (1.0f / C) - mu * mu;
    float rs  = rsqrtf(var + 1e-5f);

    float4 gg = ((const float4*)ln_g)[lane];
    float4 bb = ((const float4*)ln_b)[lane];
    float4 o;
    o.x = fmaxf((acc.x - mu) * rs * gg.x + bb.x, 0.f);
    o.y = fmaxf((acc.y - mu) * rs * gg.y + bb.y, 0.f);
    o.z = fmaxf((acc.z - mu) * rs * gg.z + bb.z, 0.f);
    o.w = fmaxf((acc.w - mu) * rs * gg.w + bb.w, 0.f);
    ((float4*)g_h0)[warp * (C / 4) + lane] = o;
}

// ---------------- edge gather + vector atomic scatter-sum ----------------
__global__ void scatter_kernel(const int* __restrict__ src,
                               const int* __restrict__ dst, int E,
                               const float* __restrict__ h,
                               float* __restrict__ agg,
                               float* __restrict__ cnt) {
    int e = (blockIdx.x * blockDim.x + threadIdx.x) >> 5;
    int lane = threadIdx.x & 31;
    if (e >= E) return;
    int s = src[e];
    int d = dst[e];
    float4 v = ((const float4*)h)[s * (C / 4) + lane];
    float* a = agg + d * C + lane * 4;
    asm volatile("red.global.add.v4.f32 [%0], {%1, %2, %3, %4};"
                 :: "l"(a), "f"(v.x), "f"(v.y), "f"(v.z), "f"(v.w) : "memory");
    if (lane == 0) atomicAdd(&cnt[d], 1.0f);
}

// ---------------- fused SAGE linear (persistent, weights staged once) ----------------
// out = relu?( [mean || self] @ [Wl;Wr]^T + bl )
// Wsh[k][j], k=0..255, stride 132 floats: compute reads (float4 over j) are
// conflict-free; staging writes are 4-way conflicted but happen once per block.
// Ish[r][k], stride 256: activation reads are warp-broadcast (all lanes same addr).
// Thread map: tx = tid&31 -> cols [4tx,4tx+4); ty = tid>>5 -> rows [TM*ty, ...).
#define WSTRIDE 132

template <int ROWS>
__global__ void __launch_bounds__(256) finalize_kernel(
    const float* __restrict__ agg, const float* __restrict__ cnt,
    const float* __restrict__ hself,
    const float* __restrict__ Wl, const float* __restrict__ bl,
    const float* __restrict__ Wr,
    float* __restrict__ out, int n, int do_relu) {
    constexpr int TM = ROWS / 8;   // rows per thread
    extern __shared__ float sm[];
    float* Wsh = sm;                        // 256 * 132 floats
    float* Ish = sm + 256 * WSTRIDE;        // ROWS * 256 floats
    const int tid = threadIdx.x;

    // ---- stage weights ONCE (global reads coalesced) ----
    for (int idx = tid; idx < C * C; idx += 256) {
        int j = idx >> 7;        // output col
        int k = idx & 127;       // input channel
        Wsh[k * WSTRIDE + j]         = Wl[idx];
        Wsh[(k + 128) * WSTRIDE + j] = Wr[idx];
    }
    __syncthreads();

    const int tx = tid & 31;
    const int ty = tid >> 5;
    const float4 bb = *(const float4*)&bl[tx * 4];
    const int ntiles = (n + ROWS - 1) / ROWS;
    const float4* agg4 = (const float4*)agg;
    const float4* hs4  = (const float4*)hself;

    for (int tile = blockIdx.x; tile < ntiles; tile += gridDim.x) {
        const int row0 = tile * ROWS;

        // ---- stage input tile: mean (k<128) || self (k>=128), float4 granularity ----
        for (int idx = tid; idx < ROWS * 64; idx += 256) {
            int r  = idx >> 6;         // local row
            int kq = idx & 63;         // float4 index within 256-float row
            int row = row0 + r;
            float4 v = make_float4(0.f, 0.f, 0.f, 0.f);
            if (row < n) {
                if (kq < 32) {
                    float4 a = agg4[row * 32 + kq];
                    float inv = 1.0f / fmaxf(cnt[row], 1.0f);
                    v.x = a.x * inv; v.y = a.y * inv; v.z = a.z * inv; v.w = a.w * inv;
                } else {
                    v = hs4[row * 32 + (kq - 32)];
                }
            }
            ((float4*)Ish)[r * 64 + kq] = v;
        }
        __syncthreads();

        // ---- register-tiled GEMM: TM rows x 4 cols per thread ----
        float acc[TM][4];
#pragma unroll
        for (int r = 0; r < TM; r++) {
            acc[r][0] = 0.f; acc[r][1] = 0.f; acc[r][2] = 0.f; acc[r][3] = 0.f;
        }
        const float* Ib = Ish + (ty * TM) * 256;
        for (int k4 = 0; k4 < 64; k4++) {
            float4 w0 = *(const float4*)&Wsh[(k4 * 4 + 0) * WSTRIDE + tx * 4];
            float4 w1 = *(const float4*)&Wsh[(k4 * 4 + 1) * WSTRIDE + tx * 4];
            float4 w2 = *(const float4*)&Wsh[(k4 * 4 + 2) * WSTRIDE + tx * 4];
            float4 w3 = *(const float4*)&Wsh[(k4 * 4 + 3) * WSTRIDE + tx * 4];
#pragma unroll
            for (int r = 0; r < TM; r++) {
                float4 a = *(const float4*)&Ib[r * 256 + k4 * 4];  // warp-broadcast
                acc[r][0] += a.x * w0.x; acc[r][1] += a.x * w0.y;
                acc[r][2] += a.x * w0.z; acc[r][3] += a.x * w0.w;
                acc[r][0] += a.y * w1.x; acc[r][1] += a.y * w1.y;
                acc[r][2] += a.y * w1.z; acc[r][3] += a.y * w1.w;
                acc[r][0] += a.z * w2.x; acc[r][1] += a.z * w2.y;
                acc[r][2] += a.z * w2.z; acc[r][3] += a.z * w2.w;
                acc[r][0] += a.w * w3.x; acc[r][1] += a.w * w3.y;
                acc[r][2] += a.w * w3.z; acc[r][3] += a.w * w3.w;
            }
        }

#pragma unroll
        for (int r = 0; r < TM; r++) {
            int row = row0 + ty * TM + r;
            if (row < n) {
                float4 o;
                o.x = acc[r][0] + bb.x;
                o.y = acc[r][1] + bb.y;
                o.z = acc[r][2] + bb.z;
                o.w = acc[r][3] + bb.w;
                if (do_relu) {
                    o.x = fmaxf(o.x, 0.f); o.y = fmaxf(o.y, 0.f);
                    o.z = fmaxf(o.z, 0.f); o.w = fmaxf(o.w, 0.f);
                }
                *(float4*)&out[row * C + tx * 4] = o;
            }
        }
        __syncthreads();   // protect Ish before next tile's staging
    }
}

// ---------------- launch ----------------
extern "C" void kernel_launch(void* const* d_in, const int* in_sizes, int n_in,
                              void* d_out, int out_size) {
    const int*   x    = (const int*)d_in[0];
    const int*   src1 = (const int*)d_in[1];
    const int*   dst1 = (const int*)d_in[2];
    const int*   src2 = (const int*)d_in[3];
    const int*   dst2 = (const int*)d_in[4];
    const float* emb  = (const float*)d_in[7];
    const float* ln_g = (const float*)d_in[8];
    const float* ln_b = (const float*)d_in[9];
    const float* Wl1  = (const float*)d_in[10];
    const float* bl1  = (const float*)d_in[11];
    const float* Wr1  = (const float*)d_in[12];
    const float* Wl2  = (const float*)d_in[13];
    const float* bl2  = (const float*)d_in[14];
    const float* Wr2  = (const float*)d_in[15];
    float* out = (float*)d_out;

    float *h0, *h1, *agg1, *cnt1, *agg2, *cnt2;
    cudaGetSymbolAddress((void**)&h0,   g_h0);
    cudaGetSymbolAddress((void**)&h1,   g_h1);
    cudaGetSymbolAddress((void**)&agg1, g_agg1);
    cudaGetSymbolAddress((void**)&cnt1, g_cnt1);
    cudaGetSymbolAddress((void**)&agg2, g_agg2);
    cudaGetSymbolAddress((void**)&cnt2, g_cnt2);

    const size_t smem64 = (size_t)(256 * WSTRIDE + 64 * 256) * sizeof(float);
    const size_t smem32 = (size_t)(256 * WSTRIDE + 32 * 256) * sizeof(float);
    cudaFuncSetAttribute(finalize_kernel<64>,
                         cudaFuncAttributeMaxDynamicSharedMemorySize, (int)smem64);
    cudaFuncSetAttribute(finalize_kernel<32>,
                         cudaFuncAttributeMaxDynamicSharedMemorySize, (int)smem32);

    const int tiles1 = (N1V + 63) / 64;   // 391
    const int tiles2 = (N2V + 31) / 32;   // 157
    const int grid1 = tiles1 < 148 ? tiles1 : 148;
    const int grid2 = tiles2 < 148 ? tiles2 : 148;

    // 1) zero aggregation buffers
    zero_kernel<<<512, 256>>>();
    // 2) embedding-bag + LN + relu -> g_h0
    embed_ln_relu<<<(N0 * 32 + 255) / 256, 256>>>(x, emb, ln_g, ln_b);
    // 3) conv1 scatter
    scatter_kernel<<<(E1V * 32 + 255) / 256, 256>>>(src1, dst1, E1V, h0, agg1, cnt1);
    // 4) conv1 linear + relu -> g_h1
    finalize_kernel<64><<<grid1, 256, smem64>>>(agg1, cnt1, h0, Wl1, bl1, Wr1, h1, N1V, 1);
    // 5) conv2 scatter
    scatter_kernel<<<(E2V * 32 + 255) / 256, 256>>>(src2, dst2, E2V, h1, agg2, cnt2);
    // 6) conv2 linear -> d_out
    finalize_kernel<32><<<grid2, 256, smem32>>>(agg2, cnt2, h1, Wl2, bl2, Wr2, out, N2V, 0);
}

// round 4
// speedup vs baseline: 1.9676x; 1.0918x over previous
#include <cuda_runtime.h>

#define N0 100000
#define WBAG 16
#define N1V 25000
#define N2V 5000
#define E1V 500000
#define E2V 100000
#define C 128

// ---------------- scratch (alloc-free rule: __device__ globals) ----------------
__device__ float g_h0[N0 * C];
__device__ float g_h1[N1V * C];
__device__ float g_mean1[N1V * C];
__device__ float g_mean2[N2V * C];
__device__ int   g_deg1[N1V];
__device__ int   g_deg2[N2V];
__device__ int   g_offs1[N1V + 1];
__device__ int   g_offs2[N2V + 1];
__device__ int   g_cur1[N1V];
__device__ int   g_cur2[N2V];
__device__ int   g_csr_src1[E1V];
__device__ int   g_csr_src2[E2V];

// ---------------- zero degree arrays ----------------
__global__ void zero_deg() {
    int i = blockIdx.x * blockDim.x + threadIdx.x;
    if (i < N1V) g_deg1[i] = 0;
    if (i < N2V) g_deg2[i] = 0;
}

// ---------------- embedding-bag sum + layernorm + relu ----------------
__global__ void embed_ln_relu(const int* __restrict__ x,
                              const float* __restrict__ emb,
                              const float* __restrict__ ln_g,
                              const float* __restrict__ ln_b) {
    int warp = (blockIdx.x * blockDim.x + threadIdx.x) >> 5;
    int lane = threadIdx.x & 31;
    if (warp >= N0) return;

    int idx_l = (lane < WBAG) ? x[warp * WBAG + lane] : 0;

    const float4* emb4 = (const float4*)emb;
    float4 acc = make_float4(0.f, 0.f, 0.f, 0.f);
#pragma unroll
    for (int w = 0; w < WBAG; w++) {
        int idx = __shfl_sync(0xffffffffu, idx_l, w);
        float4 v = emb4[idx * (C / 4) + lane];
        acc.x += v.x; acc.y += v.y; acc.z += v.z; acc.w += v.w;
    }

    float s  = acc.x + acc.y + acc.z + acc.w;
    float sq = acc.x * acc.x + acc.y * acc.y + acc.z * acc.z + acc.w * acc.w;
#pragma unroll
    for (int o = 16; o > 0; o >>= 1) {
        s  += __shfl_xor_sync(0xffffffffu, s,  o);
        sq += __shfl_xor_sync(0xffffffffu, sq, o);
    }
    float mu  = s * (1.0f / C);
    float var = sq * (1.0f / C) - mu * mu;
    float rs  = rsqrtf(var + 1e-5f);

    float4 gg = ((const float4*)ln_g)[lane];
    float4 bb = ((const float4*)ln_b)[lane];
    float4 o;
    o.x = fmaxf((acc.x - mu) * rs * gg.x + bb.x, 0.f);
    o.y = fmaxf((acc.y - mu) * rs * gg.y + bb.y, 0.f);
    o.z = fmaxf((acc.z - mu) * rs * gg.z + bb.z, 0.f);
    o.w = fmaxf((acc.w - mu) * rs * gg.w + bb.w, 0.f);
    ((float4*)g_h0)[warp * (C / 4) + lane] = o;
}

// ---------------- CSR build: histogram, scan, fill ----------------
__global__ void hist_kernel(const int* __restrict__ dst, int E, int* __restrict__ deg) {
    int e = blockIdx.x * blockDim.x + threadIdx.x;
    if (e < E) atomicAdd(&deg[dst[e]], 1);
}

// single block, 1024 threads: exclusive-scan deg -> offs[0..n], cursor = offs[0..n-1]
__global__ void __launch_bounds__(1024) scan_kernel(const int* __restrict__ deg,
                                                    int* __restrict__ offs,
                                                    int* __restrict__ cursor, int n) {
    __shared__ int wsum[32];
    __shared__ int stot;
    int tid = threadIdx.x, lane = tid & 31, wid = tid >> 5;
    int carry = 0;
    if (tid == 0) offs[0] = 0;
    for (int base = 0; base < n; base += 1024) {
        int i = base + tid;
        int v = (i < n) ? deg[i] : 0;
        int orig = v;
#pragma unroll
        for (int o = 1; o < 32; o <<= 1) {
            int t = __shfl_up_sync(0xffffffffu, v, o);
            if (lane >= o) v += t;
        }
        if (lane == 31) wsum[wid] = v;
        __syncthreads();
        if (wid == 0) {
            int s = wsum[lane];
#pragma unroll
            for (int o = 1; o < 32; o <<= 1) {
                int t = __shfl_up_sync(0xffffffffu, s, o);
                if (lane >= o) s += t;
            }
            wsum[lane] = s;
            if (lane == 31) stot = s;
        }
        __syncthreads();
        int add = carry + (wid > 0 ? wsum[wid - 1] : 0);
        if (i < n) {
            int incl = add + v;
            offs[i + 1]  = incl;
            cursor[i]    = incl - orig;
        }
        carry += stot;
        __syncthreads();
    }
}

__global__ void fill_kernel(const int* __restrict__ src, const int* __restrict__ dst,
                            int E, int* __restrict__ cursor, int* __restrict__ csr_src) {
    int e = blockIdx.x * blockDim.x + threadIdx.x;
    if (e < E) {
        int pos = atomicAdd(&cursor[dst[e]], 1);
        csr_src[pos] = src[e];
    }
}

// ---------------- CSR aggregation: warp per dst row, writes MEAN ----------------
__global__ void agg_kernel(const int* __restrict__ offs, const int* __restrict__ csr_src,
                           const float* __restrict__ h, float* __restrict__ mean, int n) {
    int row = (blockIdx.x * blockDim.x + threadIdx.x) >> 5;
    int lane = threadIdx.x & 31;
    if (row >= n) return;
    int e0 = offs[row], e1 = offs[row + 1];
    const float4* h4 = (const float4*)h;
    float4 acc = make_float4(0.f, 0.f, 0.f, 0.f);
    int e = e0;
    for (; e + 4 <= e1; e += 4) {
        int sa = csr_src[e], sb = csr_src[e + 1], sc = csr_src[e + 2], sd = csr_src[e + 3];
        float4 va = h4[sa * 32 + lane];
        float4 vb = h4[sb * 32 + lane];
        float4 vc = h4[sc * 32 + lane];
        float4 vd = h4[sd * 32 + lane];
        acc.x += va.x + vb.x + vc.x + vd.x;
        acc.y += va.y + vb.y + vc.y + vd.y;
        acc.z += va.z + vb.z + vc.z + vd.z;
        acc.w += va.w + vb.w + vc.w + vd.w;
    }
    for (; e < e1; e++) {
        float4 v = h4[csr_src[e] * 32 + lane];
        acc.x += v.x; acc.y += v.y; acc.z += v.z; acc.w += v.w;
    }
    float inv = 1.0f / fmaxf((float)(e1 - e0), 1.0f);
    float4 o = make_float4(acc.x * inv, acc.y * inv, acc.z * inv, acc.w * inv);
    ((float4*)mean)[row * 32 + lane] = o;
}

// ---------------- fused SAGE linear (chunked-K for 2 CTAs/SM) ----------------
// out = relu?( mean @ Wl^T + self @ Wr^T + bl )
// K processed in 2 chunks of 128 (chunk0: Wl/mean, chunk1: Wr/self).
// Wsh[128][132]: compute reads conflict-free; Ish[ROWS][128]: broadcast reads.
#define WSTRIDE 132

template <int ROWS>
__global__ void __launch_bounds__(256) finalize_kernel(
    const float* __restrict__ mean,
    const float* __restrict__ hself,
    const float* __restrict__ Wl, const float* __restrict__ bl,
    const float* __restrict__ Wr,
    float* __restrict__ out, int n, int do_relu) {
    constexpr int TM = ROWS / 8;   // rows per thread
    extern __shared__ float sm[];
    float* Wsh = sm;                     // 128 * 132 floats (67.6 KB)
    float* Ish = sm + 128 * WSTRIDE;     // ROWS * 128 floats
    const int tid = threadIdx.x;
    const int tx = tid & 31;
    const int ty = tid >> 5;
    const float4 bb = *(const float4*)&bl[tx * 4];
    const int ntiles = (n + ROWS - 1) / ROWS;
    const float4* mean4 = (const float4*)mean;
    const float4* hs4   = (const float4*)hself;

    for (int tile = blockIdx.x; tile < ntiles; tile += gridDim.x) {
        const int row0 = tile * ROWS;
        float acc[TM][4];
#pragma unroll
        for (int r = 0; r < TM; r++) {
            acc[r][0] = 0.f; acc[r][1] = 0.f; acc[r][2] = 0.f; acc[r][3] = 0.f;
        }

#pragma unroll
        for (int ch = 0; ch < 2; ch++) {
            __syncthreads();   // protect smem from previous chunk/tile readers
            // stage weights for this chunk: Wsh[k][j] = W[j][k]
            const float* W = ch ? Wr : Wl;
            for (int idx = tid; idx < C * C; idx += 256) {
                int j = idx >> 7;
                int k = idx & 127;
                Wsh[k * WSTRIDE + j] = W[idx];
            }
            // stage activations for this chunk (float4 granularity)
            const float4* S = ch ? hs4 : mean4;
            for (int idx = tid; idx < ROWS * 32; idx += 256) {
                int r  = idx >> 5;
                int kq = idx & 31;
                int row = row0 + r;
                float4 v = make_float4(0.f, 0.f, 0.f, 0.f);
                if (row < n) v = S[row * 32 + kq];
                ((float4*)Ish)[r * 32 + kq] = v;
            }
            __syncthreads();

            const float* Ib = Ish + (ty * TM) * 128;
            for (int k4 = 0; k4 < 32; k4++) {
                float4 w0 = *(const float4*)&Wsh[(k4 * 4 + 0) * WSTRIDE + tx * 4];
                float4 w1 = *(const float4*)&Wsh[(k4 * 4 + 1) * WSTRIDE + tx * 4];
                float4 w2 = *(const float4*)&Wsh[(k4 * 4 + 2) * WSTRIDE + tx * 4];
                float4 w3 = *(const float4*)&Wsh[(k4 * 4 + 3) * WSTRIDE + tx * 4];
#pragma unroll
                for (int r = 0; r < TM; r++) {
                    float4 a = *(const float4*)&Ib[r * 128 + k4 * 4];  // broadcast
                    acc[r][0] += a.x * w0.x; acc[r][1] += a.x * w0.y;
                    acc[r][2] += a.x * w0.z; acc[r][3] += a.x * w0.w;
                    acc[r][0] += a.y * w1.x; acc[r][1] += a.y * w1.y;
                    acc[r][2] += a.y * w1.z; acc[r][3] += a.y * w1.w;
                    acc[r][0] += a.z * w2.x; acc[r][1] += a.z * w2.y;
                    acc[r][2] += a.z * w2.z; acc[r][3] += a.z * w2.w;
                    acc[r][0] += a.w * w3.x; acc[r][1] += a.w * w3.y;
                    acc[r][2] += a.w * w3.z; acc[r][3] += a.w * w3.w;
                }
            }
        }

#pragma unroll
        for (int r = 0; r < TM; r++) {
            int row = row0 + ty * TM + r;
            if (row < n) {
                float4 o;
                o.x = acc[r][0] + bb.x;
                o.y = acc[r][1] + bb.y;
                o.z = acc[r][2] + bb.z;
                o.w = acc[r][3] + bb.w;
                if (do_relu) {
                    o.x = fmaxf(o.x, 0.f); o.y = fmaxf(o.y, 0.f);
                    o.z = fmaxf(o.z, 0.f); o.w = fmaxf(o.w, 0.f);
                }
                *(float4*)&out[row * C + tx * 4] = o;
            }
        }
    }
}

// ---------------- launch ----------------
extern "C" void kernel_launch(void* const* d_in, const int* in_sizes, int n_in,
                              void* d_out, int out_size) {
    const int*   x    = (const int*)d_in[0];
    const int*   src1 = (const int*)d_in[1];
    const int*   dst1 = (const int*)d_in[2];
    const int*   src2 = (const int*)d_in[3];
    const int*   dst2 = (const int*)d_in[4];
    const float* emb  = (const float*)d_in[7];
    const float* ln_g = (const float*)d_in[8];
    const float* ln_b = (const float*)d_in[9];
    const float* Wl1  = (const float*)d_in[10];
    const float* bl1  = (const float*)d_in[11];
    const float* Wr1  = (const float*)d_in[12];
    const float* Wl2  = (const float*)d_in[13];
    const float* bl2  = (const float*)d_in[14];
    const float* Wr2  = (const float*)d_in[15];
    float* out = (float*)d_out;

    float *h0, *h1, *mean1, *mean2;
    int *deg1, *deg2, *offs1, *offs2, *cur1, *cur2, *csr1, *csr2;
    cudaGetSymbolAddress((void**)&h0,    g_h0);
    cudaGetSymbolAddress((void**)&h1,    g_h1);
    cudaGetSymbolAddress((void**)&mean1, g_mean1);
    cudaGetSymbolAddress((void**)&mean2, g_mean2);
    cudaGetSymbolAddress((void**)&deg1,  g_deg1);
    cudaGetSymbolAddress((void**)&deg2,  g_deg2);
    cudaGetSymbolAddress((void**)&offs1, g_offs1);
    cudaGetSymbolAddress((void**)&offs2, g_offs2);
    cudaGetSymbolAddress((void**)&cur1,  g_cur1);
    cudaGetSymbolAddress((void**)&cur2,  g_cur2);
    cudaGetSymbolAddress((void**)&csr1,  g_csr_src1);
    cudaGetSymbolAddress((void**)&csr2,  g_csr_src2);

    const size_t smem64 = (size_t)(128 * WSTRIDE + 64 * 128) * sizeof(float); // ~99.6KB
    const size_t smem32 = (size_t)(128 * WSTRIDE + 32 * 128) * sizeof(float); // ~83.6KB
    cudaFuncSetAttribute(finalize_kernel<64>,
                         cudaFuncAttributeMaxDynamicSharedMemorySize, (int)smem64);
    cudaFuncSetAttribute(finalize_kernel<32>,
                         cudaFuncAttributeMaxDynamicSharedMemorySize, (int)smem32);

    const int tiles1 = (N1V + 63) / 64;   // 391
    const int tiles2 = (N2V + 31) / 32;   // 157
    const int grid1 = tiles1 < 296 ? tiles1 : 296;  // 2 CTAs/SM
    const int grid2 = tiles2 < 296 ? tiles2 : 296;

    // degree zeroing (tiny)
    zero_deg<<<(N1V + 255) / 256, 256>>>();
    // embedding-bag + LN + relu -> g_h0
    embed_ln_relu<<<(N0 * 32 + 255) / 256, 256>>>(x, emb, ln_g, ln_b);

    // ---- conv1: CSR build + aggregate + linear ----
    hist_kernel<<<(E1V + 255) / 256, 256>>>(dst1, E1V, deg1);
    scan_kernel<<<1, 1024>>>(deg1, offs1, cur1, N1V);
    fill_kernel<<<(E1V + 255) / 256, 256>>>(src1, dst1, E1V, cur1, csr1);
    agg_kernel<<<(N1V * 32 + 255) / 256, 256>>>(offs1, csr1, h0, mean1, N1V);
    finalize_kernel<64><<<grid1, 256, smem64>>>(mean1, h0, Wl1, bl1, Wr1, h1, N1V, 1);

    // ---- conv2 ----
    hist_kernel<<<(E2V + 255) / 256, 256>>>(dst2, E2V, deg2);
    scan_kernel<<<1, 1024>>>(deg2, offs2, cur2, N2V);
    fill_kernel<<<(E2V + 255) / 256, 256>>>(src2, dst2, E2V, cur2, csr2);
    agg_kernel<<<(N2V * 32 + 255) / 256, 256>>>(offs2, csr2, h1, mean2, N2V);
    finalize_kernel<32><<<grid2, 256, smem32>>>(mean2, h1, Wl2, bl2, Wr2, out, N2V, 0);
}

// round 7
// speedup vs baseline: 2.2470x; 1.1420x over previous
#include <cuda_runtime.h>

#define N0 100000
#define WBAG 16
#define N1V 25000
#define N2V 5000
#define E1V 500000
#define E2V 100000
#define C 128

// ---------------- scratch (alloc-free rule: __device__ globals) ----------------
__device__ float g_h0[N0 * C];
__device__ float g_h1[N1V * C];
__device__ float g_mean1[N1V * C];
__device__ float g_mean2[N2V * C];
__device__ int   g_deg1[N1V];
__device__ int   g_deg2[N2V];
__device__ int   g_start1[N1V];
__device__ int   g_start2[N2V];
__device__ int   g_cur1[N1V];
__device__ int   g_cur2[N2V];
__device__ int   g_csr_src1[E1V];
__device__ int   g_csr_src2[E2V];
__device__ int   g_counters[2];

// ---------------- zero degree arrays + counters ----------------
__global__ void zero_deg() {
    int i = blockIdx.x * blockDim.x + threadIdx.x;
    if (i < N1V) g_deg1[i] = 0;
    if (i < N2V) g_deg2[i] = 0;
    if (i < 2)   g_counters[i] = 0;
}

// ---------------- embedding-bag sum + layernorm + relu ----------------
__global__ void embed_ln_relu(const int* __restrict__ x,
                              const float* __restrict__ emb,
                              const float* __restrict__ ln_g,
                              const float* __restrict__ ln_b) {
    int warp = (blockIdx.x * blockDim.x + threadIdx.x) >> 5;
    int lane = threadIdx.x & 31;
    if (warp >= N0) return;

    int idx_l = (lane < WBAG) ? x[warp * WBAG + lane] : 0;

    const float4* emb4 = (const float4*)emb;
    float4 acc = make_float4(0.f, 0.f, 0.f, 0.f);
#pragma unroll
    for (int w = 0; w < WBAG; w++) {
        int idx = __shfl_sync(0xffffffffu, idx_l, w);
        float4 v = emb4[idx * (C / 4) + lane];
        acc.x += v.x; acc.y += v.y; acc.z += v.z; acc.w += v.w;
    }

    float s  = acc.x + acc.y + acc.z + acc.w;
    float sq = acc.x * acc.x + acc.y * acc.y + acc.z * acc.z + acc.w * acc.w;
#pragma unroll
    for (int o = 16; o > 0; o >>= 1) {
        s  += __shfl_xor_sync(0xffffffffu, s,  o);
        sq += __shfl_xor_sync(0xffffffffu, sq, o);
    }
    float mu  = s * (1.0f / C);
    float var = sq * (1.0f / C) - mu * mu;
    float rs  = rsqrtf(var + 1e-5f);

    float4 gg = ((const float4*)ln_g)[lane];
    float4 bb = ((const float4*)ln_b)[lane];
    float4 o;
    o.x = fmaxf((acc.x - mu) * rs * gg.x + bb.x, 0.f);
    o.y = fmaxf((acc.y - mu) * rs * gg.y + bb.y, 0.f);
    o.z = fmaxf((acc.z - mu) * rs * gg.z + bb.z, 0.f);
    o.w = fmaxf((acc.w - mu) * rs * gg.w + bb.w, 0.f);
    ((float4*)g_h0)[warp * (C / 4) + lane] = o;
}

// ---------------- merged histogram over both edge lists ----------------
__global__ void hist_kernel(const int* __restrict__ dst1, const int* __restrict__ dst2) {
    int e = blockIdx.x * blockDim.x + threadIdx.x;
    if (e < E1V) atomicAdd(&g_deg1[dst1[e]], 1);
    else if (e < E1V + E2V) atomicAdd(&g_deg2[dst2[e - E1V]], 1);
}

// ---------------- warp-aggregated offset assignment (unordered CSR ranges) ----------------
// Each subgroup (lanes of a warp belonging to the same layer, intersected with
// the VALID ballot): inclusive shfl-scan of degrees, highest valid lane grabs a
// contiguous range with ONE atomicAdd, lanes derive their starts. No ordering
// across warps is needed — CSR ranges only need to be disjoint and contiguous.
__global__ void offset_kernel() {
    int i = blockIdx.x * blockDim.x + threadIdx.x;
    int lane = threadIdx.x & 31;
    const int ntot = N1V + N2V;

    bool valid = (i < ntot);
    int layer = (valid && i >= N1V) ? 1 : 0;
    int idx = layer ? (i - N1V) : i;
    int d = 0;
    if (valid) d = layer ? g_deg2[idx] : g_deg1[idx];

    unsigned validmask = __ballot_sync(0xffffffffu, valid);
    unsigned grp       = __ballot_sync(0xffffffffu, layer == 1);
    if (!valid) return;

    // subgroup = same-layer valid lanes (contiguous within the warp)
    unsigned mymask = ((layer == 1) ? grp : ~grp) & validmask;

    // inclusive scan within subgroup (contiguity => lane-o in mask implies
    // every lane in (lane-o, lane] is in the mask)
    int incl = d;
#pragma unroll
    for (int o = 1; o < 32; o <<= 1) {
        int t = __shfl_up_sync(mymask, incl, o);
        if (lane >= o && ((mymask >> (lane - o)) & 1u)) incl += t;
    }

    int leader = 31 - __clz(mymask);          // highest VALID lane of subgroup
    int total  = __shfl_sync(mymask, incl, leader);
    int base = 0;
    if (lane == leader) base = atomicAdd(&g_counters[layer], total);
    base = __shfl_sync(mymask, base, leader);

    int start = base + incl - d;
    if (layer) { g_start2[idx] = start; g_cur2[idx] = start; }
    else       { g_start1[idx] = start; g_cur1[idx] = start; }
}

// ---------------- merged fill ----------------
__global__ void fill_kernel(const int* __restrict__ src1, const int* __restrict__ dst1,
                            const int* __restrict__ src2, const int* __restrict__ dst2) {
    int e = blockIdx.x * blockDim.x + threadIdx.x;
    if (e < E1V) {
        int pos = atomicAdd(&g_cur1[dst1[e]], 1);
        g_csr_src1[pos] = src1[e];
    } else if (e < E1V + E2V) {
        int ee = e - E1V;
        int pos = atomicAdd(&g_cur2[dst2[ee]], 1);
        g_csr_src2[pos] = src2[ee];
    }
}

// ---------------- CSR aggregation: warp per dst row, writes MEAN ----------------
__global__ void agg_kernel(const int* __restrict__ start, const int* __restrict__ deg,
                           const int* __restrict__ csr_src,
                           const float* __restrict__ h, float* __restrict__ mean, int n) {
    int row = (blockIdx.x * blockDim.x + threadIdx.x) >> 5;
    int lane = threadIdx.x & 31;
    if (row >= n) return;
    int e0 = start[row];
    int e1 = e0 + deg[row];
    const float4* h4 = (const float4*)h;
    float4 acc = make_float4(0.f, 0.f, 0.f, 0.f);
    int e = e0;
    for (; e + 4 <= e1; e += 4) {
        int sa = csr_src[e], sb = csr_src[e + 1], sc = csr_src[e + 2], sd = csr_src[e + 3];
        float4 va = h4[sa * 32 + lane];
        float4 vb = h4[sb * 32 + lane];
        float4 vc = h4[sc * 32 + lane];
        float4 vd = h4[sd * 32 + lane];
        acc.x += va.x + vb.x + vc.x + vd.x;
        acc.y += va.y + vb.y + vc.y + vd.y;
        acc.z += va.z + vb.z + vc.z + vd.z;
        acc.w += va.w + vb.w + vc.w + vd.w;
    }
    for (; e < e1; e++) {
        float4 v = h4[csr_src[e] * 32 + lane];
        acc.x += v.x; acc.y += v.y; acc.z += v.z; acc.w += v.w;
    }
    float inv = 1.0f / fmaxf((float)(e1 - e0), 1.0f);
    float4 o = make_float4(acc.x * inv, acc.y * inv, acc.z * inv, acc.w * inv);
    ((float4*)mean)[row * 32 + lane] = o;
}

// ---------------- fused SAGE linear (chunked-K for 2 CTAs/SM) ----------------
#define WSTRIDE 132

template <int ROWS>
__global__ void __launch_bounds__(256) finalize_kernel(
    const float* __restrict__ mean,
    const float* __restrict__ hself,
    const float* __restrict__ Wl, const float* __restrict__ bl,
    const float* __restrict__ Wr,
    float* __restrict__ out, int n, int do_relu) {
    constexpr int TM = ROWS / 8;
    extern __shared__ float sm[];
    float* Wsh = sm;                     // 128 * 132 floats
    float* Ish = sm + 128 * WSTRIDE;     // ROWS * 128 floats
    const int tid = threadIdx.x;
    const int tx = tid & 31;
    const int ty = tid >> 5;
    const float4 bb = *(const float4*)&bl[tx * 4];
    const int ntiles = (n + ROWS - 1) / ROWS;
    const float4* mean4 = (const float4*)mean;
    const float4* hs4   = (const float4*)hself;

    for (int tile = blockIdx.x; tile < ntiles; tile += gridDim.x) {
        const int row0 = tile * ROWS;
        float acc[TM][4];
#pragma unroll
        for (int r = 0; r < TM; r++) {
            acc[r][0] = 0.f; acc[r][1] = 0.f; acc[r][2] = 0.f; acc[r][3] = 0.f;
        }

#pragma unroll
        for (int ch = 0; ch < 2; ch++) {
            __syncthreads();
            const float* W = ch ? Wr : Wl;
            for (int idx = tid; idx < C * C; idx += 256) {
                int j = idx >> 7;
                int k = idx & 127;
                Wsh[k * WSTRIDE + j] = W[idx];
            }
            const float4* S = ch ? hs4 : mean4;
            for (int idx = tid; idx < ROWS * 32; idx += 256) {
                int r  = idx >> 5;
                int kq = idx & 31;
                int row = row0 + r;
                float4 v = make_float4(0.f, 0.f, 0.f, 0.f);
                if (row < n) v = S[row * 32 + kq];
                ((float4*)Ish)[r * 32 + kq] = v;
            }
            __syncthreads();

            const float* Ib = Ish + (ty * TM) * 128;
            for (int k4 = 0; k4 < 32; k4++) {
                float4 w0 = *(const float4*)&Wsh[(k4 * 4 + 0) * WSTRIDE + tx * 4];
                float4 w1 = *(const float4*)&Wsh[(k4 * 4 + 1) * WSTRIDE + tx * 4];
                float4 w2 = *(const float4*)&Wsh[(k4 * 4 + 2) * WSTRIDE + tx * 4];
                float4 w3 = *(const float4*)&Wsh[(k4 * 4 + 3) * WSTRIDE + tx * 4];
#pragma unroll
                for (int r = 0; r < TM; r++) {
                    float4 a = *(const float4*)&Ib[r * 128 + k4 * 4];
                    acc[r][0] += a.x * w0.x; acc[r][1] += a.x * w0.y;
                    acc[r][2] += a.x * w0.z; acc[r][3] += a.x * w0.w;
                    acc[r][0] += a.y * w1.x; acc[r][1] += a.y * w1.y;
                    acc[r][2] += a.y * w1.z; acc[r][3] += a.y * w1.w;
                    acc[r][0] += a.z * w2.x; acc[r][1] += a.z * w2.y;
                    acc[r][2] += a.z * w2.z; acc[r][3] += a.z * w2.w;
                    acc[r][0] += a.w * w3.x; acc[r][1] += a.w * w3.y;
                    acc[r][2] += a.w * w3.z; acc[r][3] += a.w * w3.w;
                }
            }
        }

#pragma unroll
        for (int r = 0; r < TM; r++) {
            int row = row0 + ty * TM + r;
            if (row < n) {
                float4 o;
                o.x = acc[r][0] + bb.x;
                o.y = acc[r][1] + bb.y;
                o.z = acc[r][2] + bb.z;
                o.w = acc[r][3] + bb.w;
                if (do_relu) {
                    o.x = fmaxf(o.x, 0.f); o.y = fmaxf(o.y, 0.f);
                    o.z = fmaxf(o.z, 0.f); o.w = fmaxf(o.w, 0.f);
                }
                *(float4*)&out[row * C + tx * 4] = o;
            }
        }
    }
}

// ---------------- launch ----------------
extern "C" void kernel_launch(void* const* d_in, const int* in_sizes, int n_in,
                              void* d_out, int out_size) {
    const int*   x    = (const int*)d_in[0];
    const int*   src1 = (const int*)d_in[1];
    const int*   dst1 = (const int*)d_in[2];
    const int*   src2 = (const int*)d_in[3];
    const int*   dst2 = (const int*)d_in[4];
    const float* emb  = (const float*)d_in[7];
    const float* ln_g = (const float*)d_in[8];
    const float* ln_b = (const float*)d_in[9];
    const float* Wl1  = (const float*)d_in[10];
    const float* bl1  = (const float*)d_in[11];
    const float* Wr1  = (const float*)d_in[12];
    const float* Wl2  = (const float*)d_in[13];
    const float* bl2  = (const float*)d_in[14];
    const float* Wr2  = (const float*)d_in[15];
    float* out = (float*)d_out;

    float *h0, *h1, *mean1, *mean2;
    int *deg1, *deg2, *start1, *start2, *csr1, *csr2;
    cudaGetSymbolAddress((void**)&h0,     g_h0);
    cudaGetSymbolAddress((void**)&h1,     g_h1);
    cudaGetSymbolAddress((void**)&mean1,  g_mean1);
    cudaGetSymbolAddress((void**)&mean2,  g_mean2);
    cudaGetSymbolAddress((void**)&deg1,   g_deg1);
    cudaGetSymbolAddress((void**)&deg2,   g_deg2);
    cudaGetSymbolAddress((void**)&start1, g_start1);
    cudaGetSymbolAddress((void**)&start2, g_start2);
    cudaGetSymbolAddress((void**)&csr1,   g_csr_src1);
    cudaGetSymbolAddress((void**)&csr2,   g_csr_src2);

    const size_t smem64 = (size_t)(128 * WSTRIDE + 64 * 128) * sizeof(float);
    const size_t smem32 = (size_t)(128 * WSTRIDE + 32 * 128) * sizeof(float);
    cudaFuncSetAttribute(finalize_kernel<64>,
                         cudaFuncAttributeMaxDynamicSharedMemorySize, (int)smem64);
    cudaFuncSetAttribute(finalize_kernel<32>,
                         cudaFuncAttributeMaxDynamicSharedMemorySize, (int)smem32);

    const int tiles1 = (N1V + 63) / 64;
    const int tiles2 = (N2V + 31) / 32;
    const int grid1 = tiles1 < 296 ? tiles1 : 296;
    const int grid2 = tiles2 < 296 ? tiles2 : 296;

    // CSR build (both layers merged)
    zero_deg<<<(N1V + 255) / 256, 256>>>();
    hist_kernel<<<(E1V + E2V + 255) / 256, 256>>>(dst1, dst2);
    offset_kernel<<<(N1V + N2V + 31 + 255) / 256, 256>>>();
    fill_kernel<<<(E1V + E2V + 255) / 256, 256>>>(src1, dst1, src2, dst2);

    // embedding-bag + LN + relu -> g_h0
    embed_ln_relu<<<(N0 * 32 + 255) / 256, 256>>>(x, emb, ln_g, ln_b);

    // conv1
    agg_kernel<<<(N1V * 32 + 255) / 256, 256>>>(start1, deg1, csr1, h0, mean1, N1V);
    finalize_kernel<64><<<grid1, 256, smem64>>>(mean1, h0, Wl1, bl1, Wr1, h1, N1V, 1);

    // conv2
    agg_kernel<<<(N2V * 32 + 255) / 256, 256>>>(start2, deg2, csr2, h1, mean2, N2V);
    finalize_kernel<32><<<grid2, 256, smem32>>>(mean2, h1, Wl2, bl2, Wr2, out, N2V, 0);
}